// round 13
// baseline (speedup 1.0000x reference)
#include <cuda_runtime.h>
#include <cstdint>

// Problem constants
#define BTOK  65536
#define HID   512
#define DIN   512
#define NEXP  64
#define FOURE 256

// ---------------- scratch (static __device__, no allocation) ----------------
__device__ float g_q1[(size_t)BTOK * HID];   // qe1 output, reused for fused
__device__ float g_q [(size_t)BTOK * HID];   // qe2 output
__device__ float g_t [(size_t)BTOK * FOURE]; // tanh(fused @ Wg1^T)
__device__ float g_l [(size_t)BTOK * NEXP];  // logits

// ---------------- packed f32x2 helpers (sm_103a) ----------------------------
typedef unsigned long long u64;

__device__ __forceinline__ u64 fma2(u64 a, u64 b, u64 c) {
    u64 d;
    asm("fma.rn.f32x2 %0, %1, %2, %3;" : "=l"(d) : "l"(a), "l"(b), "l"(c));
    return d;
}
__device__ __forceinline__ u64 add2(u64 a, u64 b) {
    u64 d;
    asm("add.rn.f32x2 %0, %1, %2;" : "=l"(d) : "l"(a), "l"(b));
    return d;
}
__device__ __forceinline__ u64 dup2(float x) {
    u64 d;
    asm("mov.b64 %0, {%1, %1};" : "=l"(d) : "f"(x));
    return d;
}
__device__ __forceinline__ float2 unpk2(u64 a) {
    float2 r;
    asm("mov.b64 {%0, %1}, %2;" : "=f"(r.x), "=f"(r.y) : "l"(a));
    return r;
}

// ---------------- chunked-Kahan double-buffered fp32 GEMM -------------------
// 256-thread blocks, BM=64, BN=16*NCOL, 2 blocks/SM -> 16 warps/SM (latency
// cover) with per-thread tile 4 rows (2 packed pairs) x NCOL cols -> 96 accum
// regs, total ~125 < 128-reg cap. Double-buffered smem + register prefetch.
// Chunk numerics (16-term ascending plain-FMA chunks, packed Kahan fold with
// Cn = -compensation) bit-identical to the previous passing rounds.
// A is logically [M, K]; columns [0,K0) from A0 (row stride K0), columns
// [K0,K) from A1 (row stride K-K0).  W is [N, K] row-major.

#define LDG_TILE(kt)                                                          \
    {                                                                         \
        {                                                                     \
            const int ar = tid >> 2;                                          \
            const int ac = (tid & 3) << 2;                                    \
            const int gk = (kt) + ac;                                         \
            rA = (gk < K0)                                                    \
                ? *(const float4*)(A0 + (size_t)(m0 + ar) * K0 + gk)          \
                : *(const float4*)(A1 + (size_t)(m0 + ar) * (K - K0) + (gk - K0)); \
        }                                                                     \
        _Pragma("unroll")                                                     \
        for (int c = 0; c < CB; c++) {                                        \
            const int fidx = CB * tid + c;                                    \
            const int br = fidx >> 2;                                         \
            const int bc = (fidx & 3) << 2;                                   \
            rB[c] = *(const float4*)(W + (size_t)(n0 + br) * K + (kt) + bc);  \
        }                                                                     \
    }

#define STS_TILE(buf)                                                         \
    {                                                                         \
        {                                                                     \
            const int ar = tid >> 2;                                          \
            const int ac = (tid & 3) << 2;                                    \
            As[buf][ac + 0][ar] = rA.x;                                       \
            As[buf][ac + 1][ar] = rA.y;                                       \
            As[buf][ac + 2][ar] = rA.z;                                       \
            As[buf][ac + 3][ar] = rA.w;                                       \
        }                                                                     \
        _Pragma("unroll")                                                     \
        for (int c = 0; c < CB; c++) {                                        \
            const int fidx = CB * tid + c;                                    \
            const int br = fidx >> 2;                                         \
            const int bc = (fidx & 3) << 2;                                   \
            Bs[buf][bc + 0][br] = rB[c].x;                                    \
            Bs[buf][bc + 1][br] = rB[c].y;                                    \
            Bs[buf][bc + 2][br] = rB[c].z;                                    \
            Bs[buf][bc + 3][br] = rB[c].w;                                    \
        }                                                                     \
    }

template <int NCOL>
__global__ void __launch_bounds__(256, 2) gemm_db(
    const float* __restrict__ A0, const float* __restrict__ A1, int K0, int K,
    const float* __restrict__ W, const float* __restrict__ bias,
    float* __restrict__ C, int N, int act)
{
    constexpr int BN = 16 * NCOL;
    constexpr int CB = BN / 64;           // B float4 loads per thread (256 thr)
    __shared__ __align__(16) float As[2][16][64];
    __shared__ __align__(16) float Bs[2][16][BN];

    const int tid  = threadIdx.x;
    const int m0   = blockIdx.y * 64;
    const int n0   = blockIdx.x * BN;
    const int trow = (tid >> 4) << 2;     // 0..60 step 4 (2 row pairs)
    const int tcol = tid & 15;            // 0..15; cols tcol + 16*j

    const u64 MONE = 0xbf800000bf800000ULL;  // (-1.0f, -1.0f)

    u64 S[2][NCOL], Cn[2][NCOL];
#pragma unroll
    for (int pi = 0; pi < 2; pi++)
#pragma unroll
        for (int j = 0; j < NCOL; j++) { S[pi][j] = 0ull; Cn[pi][j] = 0ull; }

    float4 rA, rB[CB];

    LDG_TILE(0);
    STS_TILE(0);
    __syncthreads();

    int p = 0;
    for (int kt = 0; kt < K; kt += 16) {
        const bool nxt = (kt + 16) < K;
        if (nxt) LDG_TILE(kt + 16);

        // 16-term chunk: plain packed FMA into P (independent chains)
        u64 P[2][NCOL];
#pragma unroll
        for (int pi = 0; pi < 2; pi++)
#pragma unroll
            for (int j = 0; j < NCOL; j++) P[pi][j] = 0ull;

#pragma unroll
        for (int k = 0; k < 16; k++) {
            u64 ap[2];
#pragma unroll
            for (int pi = 0; pi < 2; pi++)
                ap[pi] = *(const u64*)&As[p][k][trow + 2 * pi];  // LDS.64 bcast
#pragma unroll
            for (int j = 0; j < NCOL; j++) {
                const u64 bd = dup2(Bs[p][k][tcol + 16 * j]);    // LDS.32 cf
#pragma unroll
                for (int pi = 0; pi < 2; pi++)
                    P[pi][j] = fma2(ap[pi], bd, P[pi][j]);
            }
        }

        // Kahan fold of chunk sums into (S, Cn)
#pragma unroll
        for (int pi = 0; pi < 2; pi++)
#pragma unroll
            for (int j = 0; j < NCOL; j++) {
                u64 y = add2(P[pi][j], Cn[pi][j]);
                u64 t = add2(S[pi][j], y);
                u64 u = fma2(t, MONE, S[pi][j]);   // s - t (exact)
                Cn[pi][j] = add2(y, u);            // y - (t - s)
                S[pi][j]  = t;
            }

        if (nxt) {
            STS_TILE(p ^ 1);
            __syncthreads();
        }
        p ^= 1;
    }

    float bb[NCOL];
#pragma unroll
    for (int j = 0; j < NCOL; j++) bb[j] = bias ? bias[n0 + tcol + 16 * j] : 0.f;

#pragma unroll
    for (int pi = 0; pi < 2; pi++) {
        float* cp0 = C + (size_t)(m0 + trow + 2 * pi)     * N + n0 + tcol;
        float* cp1 = C + (size_t)(m0 + trow + 2 * pi + 1) * N + n0 + tcol;
#pragma unroll
        for (int j = 0; j < NCOL; j++) {
            float2 v = unpk2(S[pi][j]);
            float xl = v.x + bb[j];
            float xh = v.y + bb[j];
            if (act == 1)      { xl = fmaxf(xl, 0.f); xh = fmaxf(xh, 0.f); }
            else if (act == 2) { xl = tanhf(xl);      xh = tanhf(xh); }
            cp0[16 * j] = xl;
            cp1[16 * j] = xh;
        }
    }
}

// ---------------- epilogue: softmax + top2 + scatter (memory-bound) ---------
#define EPI_THREADS 256   // 8 warps -> 8 tokens per block

__global__ __launch_bounds__(EPI_THREADS) void epilogue_kernel(
    float* __restrict__ out, int out_size)
{
    const int tid  = threadIdx.x;
    const int lane = tid & 31;
    const int warp = tid >> 5;
    const int b    = blockIdx.x * (EPI_THREADS / 32) + warp;

    const int  OFF_L = BTOK * NEXP;
    const int  OFF_W = 2 * BTOK * NEXP;
    const int  OFF_I = 3 * BTOK * NEXP;
    const bool wl = out_size >= OFF_W;
    const bool ww = out_size >= OFF_I;
    const bool wi = out_size >= OFF_I + 2 * BTOK;

    const size_t base = (size_t)b * NEXP;
    const float l0 = g_l[base + lane];
    const float l1 = g_l[base + lane + 32];

    // softmax over 64
    float m = fmaxf(l0, l1);
#pragma unroll
    for (int off = 16; off; off >>= 1)
        m = fmaxf(m, __shfl_xor_sync(0xffffffffu, m, off));
    const float e0 = expf(l0 - m);
    const float e1 = expf(l1 - m);
    float sden = e0 + e1;
#pragma unroll
    for (int off = 16; off; off >>= 1)
        sden += __shfl_xor_sync(0xffffffffu, sden, off);
    const float w0 = e0 / sden;
    const float w1 = e1 / sden;

    // top-1 (lower index wins ties -> matches jax.lax.top_k)
    float bv; int bi;
    if (w0 >= w1) { bv = w0; bi = lane; } else { bv = w1; bi = lane + 32; }
#pragma unroll
    for (int off = 16; off; off >>= 1) {
        float ov = __shfl_xor_sync(0xffffffffu, bv, off);
        int   oi = __shfl_xor_sync(0xffffffffu, bi, off);
        if (ov > bv || (ov == bv && oi < bi)) { bv = ov; bi = oi; }
    }
    // top-2 (exclude bi; weights >= 0 so -1 acts as -inf)
    float d0 = (lane == bi)      ? -1.f : w0;
    float d1 = (lane + 32 == bi) ? -1.f : w1;
    float bv2; int bi2;
    if (d0 >= d1) { bv2 = d0; bi2 = lane; } else { bv2 = d1; bi2 = lane + 32; }
#pragma unroll
    for (int off = 16; off; off >>= 1) {
        float ov = __shfl_xor_sync(0xffffffffu, bv2, off);
        int   oi = __shfl_xor_sync(0xffffffffu, bi2, off);
        if (ov > bv2 || (ov == bv2 && oi < bi2)) { bv2 = ov; bi2 = oi; }
    }

    const float denom = bv + bv2 + 1e-6f;
    const float r1 = bv / denom;
    const float r2 = bv2 / denom;

    const float cA = (lane == bi)      ? r1 : (lane == bi2)      ? r2 : 0.f;
    const float cB = (lane + 32 == bi) ? r1 : (lane + 32 == bi2) ? r2 : 0.f;
    out[base + lane]      = cA;
    out[base + lane + 32] = cB;
    if (wl) { out[OFF_L + base + lane] = l0; out[OFF_L + base + lane + 32] = l1; }
    if (ww) { out[OFF_W + base + lane] = w0; out[OFF_W + base + lane + 32] = w1; }
    if (wi && lane == 0) {
        out[OFF_I + (size_t)b * 2]     = (float)bi;
        out[OFF_I + (size_t)b * 2 + 1] = (float)bi2;
    }
}

// ---------------- launch ----------------------------------------------------
extern "C" void kernel_launch(void* const* d_in, const int* in_sizes, int n_in,
                              void* d_out, int out_size)
{
    const float* mm    = (const float*)d_in[0];
    const float* qf    = (const float*)d_in[1];
    const float* W_qe1 = (const float*)d_in[2];
    const float* b_qe1 = (const float*)d_in[3];
    const float* W_qe2 = (const float*)d_in[4];
    const float* b_qe2 = (const float*)d_in[5];
    const float* W_fus = (const float*)d_in[6];
    const float* b_fus = (const float*)d_in[7];
    const float* W_g1  = (const float*)d_in[8];
    const float* W_g2  = (const float*)d_in[9];
    float* out = (float*)d_out;

    float *p_q1, *p_q, *p_t, *p_l;
    cudaGetSymbolAddress((void**)&p_q1, g_q1);
    cudaGetSymbolAddress((void**)&p_q,  g_q);
    cudaGetSymbolAddress((void**)&p_t,  g_t);
    cudaGetSymbolAddress((void**)&p_l,  g_l);

    const dim3 blk(256);
    const int mblocks = BTOK / 64;   // 1024

    // q1 = relu(qf @ W_qe1^T + b_qe1)          N=512 -> BN=128
    gemm_db<8><<<dim3(HID / 128, mblocks), blk>>>(
        qf, nullptr, DIN, DIN, W_qe1, b_qe1, p_q1, HID, 1);
    // q = q1 @ W_qe2^T + b_qe2                 N=512
    gemm_db<8><<<dim3(HID / 128, mblocks), blk>>>(
        p_q1, nullptr, HID, HID, W_qe2, b_qe2, p_q, HID, 0);
    // fused = relu([mm | q] @ W_fus^T + b_fus) N=512, K=1024 (reuses g_q1)
    gemm_db<8><<<dim3(HID / 128, mblocks), blk>>>(
        mm, p_q, HID, 2 * HID, W_fus, b_fus, p_q1, HID, 1);
    // t = tanh(fused @ W_g1^T)                 N=256
    gemm_db<8><<<dim3(FOURE / 128, mblocks), blk>>>(
        p_q1, nullptr, HID, HID, W_g1, nullptr, p_t, FOURE, 2);
    // logits = t @ W_g2^T                      N=64 -> BN=64 variant
    gemm_db<4><<<dim3(NEXP / 64, mblocks), blk>>>(
        p_t, nullptr, FOURE, FOURE, W_g2, nullptr, p_l, NEXP, 0);

    // softmax + top2 + scatter (memory-bound)
    epilogue_kernel<<<BTOK / (EPI_THREADS / 32), EPI_THREADS>>>(out, out_size);
}

// round 15
// speedup vs baseline: 1.6587x; 1.6587x over previous
#include <cuda_runtime.h>
#include <cuda_bf16.h>
#include <cstdint>

#define BTOK  65536
#define HID   512
#define DIN   512
#define NEXP  64
#define FOURE 256
#define TAU   2e-5f

typedef __nv_bfloat16 bf16;
typedef unsigned int u32;

// ---------------- scratch (static __device__, no allocation) ----------------
__device__ __align__(16) bf16 g_qfh[(size_t)BTOK * DIN];
__device__ __align__(16) bf16 g_qfl[(size_t)BTOK * DIN];
__device__ __align__(16) bf16 g_mmh[(size_t)BTOK * HID];
__device__ __align__(16) bf16 g_mml[(size_t)BTOK * HID];
__device__ __align__(16) bf16 g_x1h[(size_t)BTOK * HID];
__device__ __align__(16) bf16 g_x1l[(size_t)BTOK * HID];
__device__ __align__(16) bf16 g_x2h[(size_t)BTOK * HID];
__device__ __align__(16) bf16 g_x2l[(size_t)BTOK * HID];
__device__ __align__(16) bf16 g_x3h[(size_t)BTOK * HID];
__device__ __align__(16) bf16 g_x3l[(size_t)BTOK * HID];
__device__ __align__(16) bf16 g_x4h[(size_t)BTOK * FOURE];
__device__ __align__(16) bf16 g_x4l[(size_t)BTOK * FOURE];
__device__ __align__(16) bf16 g_w1h[(size_t)HID * DIN];
__device__ __align__(16) bf16 g_w1l[(size_t)HID * DIN];
__device__ __align__(16) bf16 g_w2h[(size_t)HID * HID];
__device__ __align__(16) bf16 g_w2l[(size_t)HID * HID];
__device__ __align__(16) bf16 g_wfh[(size_t)HID * 2 * HID];
__device__ __align__(16) bf16 g_wfl[(size_t)HID * 2 * HID];
__device__ __align__(16) bf16 g_g1h[(size_t)FOURE * HID];
__device__ __align__(16) bf16 g_g1l[(size_t)FOURE * HID];
__device__ __align__(16) bf16 g_g2h[(size_t)NEXP * FOURE];
__device__ __align__(16) bf16 g_g2l[(size_t)NEXP * FOURE];
__device__ float g_l[(size_t)BTOK * NEXP];
__device__ int   g_list[BTOK];
__device__ int   g_count;

// ---------------- helpers ----------------------------------------------------
__device__ __forceinline__ u32 smem_u32(const void* p) {
    u32 a;
    asm("{ .reg .u64 t; cvta.to.shared.u64 t, %1; cvt.u32.u64 %0, t; }" : "=r"(a) : "l"(p));
    return a;
}
// swizzled byte offset inside a [rows][32 bf16] tile (row stride 64B).
// cblock xor (row>>1)&3 -> all 8-row ldmatrix phases conflict-free.
__device__ __forceinline__ int swoff(int r, int c8) {
    return r * 64 + ((((c8 >> 3) ^ ((r >> 1) & 3)) & 3) << 4);
}
__device__ __forceinline__ void ldsm4(u32* r, u32 a) {
    asm volatile("ldmatrix.sync.aligned.m8n8.x4.shared.b16 {%0,%1,%2,%3}, [%4];"
                 : "=r"(r[0]), "=r"(r[1]), "=r"(r[2]), "=r"(r[3]) : "r"(a));
}
__device__ __forceinline__ void hmma(float* d, const u32* a, u32 b0, u32 b1) {
    asm volatile(
        "mma.sync.aligned.m16n8k16.row.col.f32.bf16.bf16.f32 "
        "{%0,%1,%2,%3}, {%4,%5,%6,%7}, {%8,%9}, {%0,%1,%2,%3};"
        : "+f"(d[0]), "+f"(d[1]), "+f"(d[2]), "+f"(d[3])
        : "r"(a[0]), "r"(a[1]), "r"(a[2]), "r"(a[3]), "r"(b0), "r"(b1));
}

// ---------------- split fp32 -> hi/lo bf16 -----------------------------------
__global__ void split2(const float* __restrict__ x, bf16* __restrict__ h,
                       bf16* __restrict__ l, int n)
{
    int i = blockIdx.x * blockDim.x + threadIdx.x;
    if (i >= n) return;
    float v = x[i];
    bf16 a = __float2bfloat16(v);
    h[i] = a;
    l[i] = __float2bfloat16(v - __bfloat162float(a));
}

__global__ void zero_cnt() { g_count = 0; }

// ---------------- HMMA bf16x2-split layer: C = act(A @ W^T + b) --------------
// CTA 128x64 (8 warps, warp tile 32x32), K tiles of 32. 3 products per k16:
// (hi,hi), (hi,lo), (lo,hi); fp32 accumulate. A = a0|a1 segments at K0.
struct LArgs {
    const bf16 *a0h, *a0l, *a1h, *a1l;
    const bf16 *bh, *bl;
    const float* bias;
    bf16 *oh, *ol;
    float* of;
    int K0, K, N, act, outf;
};

__global__ void __launch_bounds__(256, 2) mma_layer(LArgs ar)
{
    __shared__ __align__(16) bf16 As[2][128 * 32];
    __shared__ __align__(16) bf16 Bs[2][64 * 32];
    const int tid = threadIdx.x, wid = tid >> 5, lane = tid & 31;
    const int m0 = blockIdx.y * 128, n0 = blockIdx.x * 64;
    const int mbase = (wid & 3) * 32, nbase = (wid >> 2) * 32;

    float acc[2][4][4];
#pragma unroll
    for (int i = 0; i < 2; i++)
#pragma unroll
        for (int j = 0; j < 4; j++)
#pragma unroll
            for (int c = 0; c < 4; c++) acc[i][j][c] = 0.f;

    const u32 asb0 = smem_u32(As[0]), asb1 = smem_u32(As[1]);
    const u32 bsb0 = smem_u32(Bs[0]), bsb1 = smem_u32(Bs[1]);

    for (int kt = 0; kt < ar.K; kt += 32) {
        const bool s0 = kt < ar.K0;
        const int stride = s0 ? ar.K0 : (ar.K - ar.K0);
        const int goff = s0 ? kt : (kt - ar.K0);
        const bf16* ah = s0 ? ar.a0h : ar.a1h;
        const bf16* al = s0 ? ar.a0l : ar.a1l;
        __syncthreads();
#pragma unroll
        for (int c = 0; c < 2; c++) {
            int fidx = c * 256 + tid, r = fidx >> 2, c8 = (fidx & 3) * 8;
            const size_t go = (size_t)(m0 + r) * stride + goff + c8;
            *(uint4*)((char*)As[0] + swoff(r, c8)) = *(const uint4*)(ah + go);
            *(uint4*)((char*)As[1] + swoff(r, c8)) = *(const uint4*)(al + go);
        }
        {
            int r = tid >> 2, c8 = (tid & 3) * 8;
            const size_t go = (size_t)(n0 + r) * ar.K + kt + c8;
            *(uint4*)((char*)Bs[0] + swoff(r, c8)) = *(const uint4*)(ar.bh + go);
            *(uint4*)((char*)Bs[1] + swoff(r, c8)) = *(const uint4*)(ar.bl + go);
        }
        __syncthreads();

#pragma unroll
        for (int kh = 0; kh < 32; kh += 16) {
            u32 a[2][2][4], b[2][2][4];
            {
                const int rr = (lane & 7) + ((lane >> 3) & 1) * 8;
                const int c8 = kh + (lane >> 4) * 8;
#pragma unroll
                for (int i = 0; i < 2; i++) {
                    const int off = swoff(mbase + i * 16 + rr, c8);
                    ldsm4(a[0][i], asb0 + off);
                    ldsm4(a[1][i], asb1 + off);
                }
            }
            {
                const int mi = lane >> 3;
#pragma unroll
                for (int pb = 0; pb < 2; pb++) {
                    const int row = nbase + (pb * 2 + (mi >> 1)) * 8 + (lane & 7);
                    const int c8 = kh + (mi & 1) * 8;
                    const int off = swoff(row, c8);
                    ldsm4(b[0][pb], bsb0 + off);
                    ldsm4(b[1][pb], bsb1 + off);
                }
            }
#pragma unroll
            for (int p = 0; p < 3; p++) {
                const int sa = (p == 2) ? 1 : 0;
                const int sb = (p == 1) ? 1 : 0;
#pragma unroll
                for (int i = 0; i < 2; i++)
#pragma unroll
                    for (int j = 0; j < 4; j++) {
                        const int pb = j >> 1, ix = (j & 1) * 2;
                        hmma(acc[i][j], a[sa][i], b[sb][pb][ix], b[sb][pb][ix + 1]);
                    }
            }
        }
    }

    // epilogue: bias + act, write hi/lo splits (or f32 for logits)
    const int g = lane >> 2, t = lane & 3;
#pragma unroll
    for (int i = 0; i < 2; i++)
#pragma unroll
        for (int j = 0; j < 4; j++) {
            const int col = n0 + nbase + j * 8 + 2 * t;
            const float bb0 = ar.bias ? ar.bias[col] : 0.f;
            const float bb1 = ar.bias ? ar.bias[col + 1] : 0.f;
#pragma unroll
            for (int h = 0; h < 2; h++) {
                const int R = m0 + mbase + i * 16 + g + h * 8;
                float v0 = acc[i][j][h * 2 + 0] + bb0;
                float v1 = acc[i][j][h * 2 + 1] + bb1;
                if (ar.act == 1)      { v0 = fmaxf(v0, 0.f); v1 = fmaxf(v1, 0.f); }
                else if (ar.act == 2) { v0 = tanhf(v0);      v1 = tanhf(v1); }
                const size_t o = (size_t)R * ar.N + col;
                if (ar.outf) {
                    *(float2*)(ar.of + o) = make_float2(v0, v1);
                } else {
                    bf16 h0 = __float2bfloat16(v0), h1 = __float2bfloat16(v1);
                    __nv_bfloat162 hv; hv.x = h0; hv.y = h1;
                    *(__nv_bfloat162*)(ar.oh + o) = hv;
                    __nv_bfloat162 lv;
                    lv.x = __float2bfloat16(v0 - __bfloat162float(h0));
                    lv.y = __float2bfloat16(v1 - __bfloat162float(h1));
                    *(__nv_bfloat162*)(ar.ol + o) = lv;
                }
            }
        }
}

// ---------------- warp softmax/top2 ------------------------------------------
__device__ __forceinline__ void top2_write(float l0, float l1, int lane, int b,
                                           float* out, int out_size, bool flag_mode)
{
    const int OFF_L = BTOK * NEXP, OFF_W = 2 * BTOK * NEXP, OFF_I = 3 * BTOK * NEXP;
    const bool wl = out_size >= OFF_W, ww = out_size >= OFF_I;
    const bool wi = out_size >= OFF_I + 2 * BTOK;

    float m = fmaxf(l0, l1);
#pragma unroll
    for (int o = 16; o; o >>= 1) m = fmaxf(m, __shfl_xor_sync(0xffffffffu, m, o));
    float e0 = expf(l0 - m), e1 = expf(l1 - m);
    float sd = e0 + e1;
#pragma unroll
    for (int o = 16; o; o >>= 1) sd += __shfl_xor_sync(0xffffffffu, sd, o);
    float w0 = e0 / sd, w1 = e1 / sd;

    float bv; int bi;
    if (w0 >= w1) { bv = w0; bi = lane; } else { bv = w1; bi = lane + 32; }
#pragma unroll
    for (int o = 16; o; o >>= 1) {
        float ov = __shfl_xor_sync(0xffffffffu, bv, o);
        int oi = __shfl_xor_sync(0xffffffffu, bi, o);
        if (ov > bv || (ov == bv && oi < bi)) { bv = ov; bi = oi; }
    }
    float d0 = (lane == bi) ? -1.f : w0;
    float d1 = (lane + 32 == bi) ? -1.f : w1;
    float bv2; int bi2;
    if (d0 >= d1) { bv2 = d0; bi2 = lane; } else { bv2 = d1; bi2 = lane + 32; }
#pragma unroll
    for (int o = 16; o; o >>= 1) {
        float ov = __shfl_xor_sync(0xffffffffu, bv2, o);
        int oi = __shfl_xor_sync(0xffffffffu, bi2, o);
        if (ov > bv2 || (ov == bv2 && oi < bi2)) { bv2 = ov; bi2 = oi; }
    }
    if (flag_mode) {
        float f0 = (lane == bi || lane == bi2) ? -1.f : w0;
        float f1 = (lane + 32 == bi || lane + 32 == bi2) ? -1.f : w1;
        float bv3 = fmaxf(f0, f1);
#pragma unroll
        for (int o = 16; o; o >>= 1) bv3 = fmaxf(bv3, __shfl_xor_sync(0xffffffffu, bv3, o));
        if (lane == 0 && (bv - bv2 < TAU || bv2 - bv3 < TAU)) {
            int p = atomicAdd(&g_count, 1);
            if (p < BTOK) g_list[p] = b;
        }
    }
    const float den = bv + bv2 + 1e-6f;
    const float r1 = bv / den, r2 = bv2 / den;
    const size_t base = (size_t)b * NEXP;
    out[base + lane]      = (lane == bi) ? r1 : (lane == bi2) ? r2 : 0.f;
    out[base + lane + 32] = (lane + 32 == bi) ? r1 : (lane + 32 == bi2) ? r2 : 0.f;
    if (wl) { out[OFF_L + base + lane] = l0; out[OFF_L + base + lane + 32] = l1; }
    if (ww) { out[OFF_W + base + lane] = w0; out[OFF_W + base + lane + 32] = w1; }
    if (wi && lane == 0) {
        out[OFF_I + (size_t)b * 2]     = (float)bi;
        out[OFF_I + (size_t)b * 2 + 1] = (float)bi2;
    }
}

__global__ __launch_bounds__(256) void epilogue_kernel(float* __restrict__ out, int out_size)
{
    const int lane = threadIdx.x & 31;
    const int b = blockIdx.x * 8 + (threadIdx.x >> 5);
    const size_t base = (size_t)b * NEXP;
    top2_write(g_l[base + lane], g_l[base + lane + 32], lane, b, out, out_size, true);
}

// ---------------- exact path: warp-cooperative Kahan recompute ---------------
__device__ __forceinline__ void wdot2(const float* __restrict__ x,
                                      const float* __restrict__ w0,
                                      const float* __restrict__ w1,
                                      int K, int lane, float& r0, float& r1)
{
    float s0 = 0.f, c0 = 0.f, s1 = 0.f, c1 = 0.f;
    for (int k = lane; k < K; k += 32) {
        const float xv = x[k];
        { float y = fmaf(xv, w0[k], -c0); float t = s0 + y; c0 = (t - s0) - y; s0 = t; }
        { float y = fmaf(xv, w1[k], -c1); float t = s1 + y; c1 = (t - s1) - y; s1 = t; }
    }
    s0 -= c0; s1 -= c1;
#pragma unroll
    for (int o = 16; o; o >>= 1) {
        s0 += __shfl_xor_sync(0xffffffffu, s0, o);
        s1 += __shfl_xor_sync(0xffffffffu, s1, o);
    }
    r0 = s0; r1 = s1;
}

__global__ __launch_bounds__(256) void exact_fix(
    const float* mm, const float* qf,
    const float* W1, const float* b1, const float* W2, const float* b2,
    const float* Wf, const float* bfu, const float* Wg1, const float* Wg2,
    float* out, int out_size)
{
    __shared__ float sA[8][1024];
    __shared__ float sB[8][512];
    const int wid = threadIdx.x >> 5, lane = threadIdx.x & 31;
    const int cnt = g_count;
    for (int base = blockIdx.x * 8; base < cnt; base += gridDim.x * 8) {
        const int idx = base + wid;
        if (idx < cnt) {
            const int b = g_list[idx];
            float* xa = sA[wid];
            float* xb = sB[wid];
            for (int k = lane; k < DIN; k += 32) xa[k] = qf[(size_t)b * DIN + k];
            __syncwarp();
            for (int n = 0; n < HID; n += 2) {
                float d0, d1;
                wdot2(xa, W1 + (size_t)n * DIN, W1 + (size_t)(n + 1) * DIN, DIN, lane, d0, d1);
                if (lane == 0) {
                    xb[n] = fmaxf(d0 + b1[n], 0.f);
                    xb[n + 1] = fmaxf(d1 + b1[n + 1], 0.f);
                }
            }
            __syncwarp();
            for (int n = 0; n < HID; n += 2) {
                float d0, d1;
                wdot2(xb, W2 + (size_t)n * HID, W2 + (size_t)(n + 1) * HID, HID, lane, d0, d1);
                if (lane == 0) { xa[HID + n] = d0 + b2[n]; xa[HID + n + 1] = d1 + b2[n + 1]; }
            }
            __syncwarp();
            for (int k = lane; k < HID; k += 32) xa[k] = mm[(size_t)b * HID + k];
            __syncwarp();
            for (int n = 0; n < HID; n += 2) {
                float d0, d1;
                wdot2(xa, Wf + (size_t)n * 2 * HID, Wf + (size_t)(n + 1) * 2 * HID, 2 * HID, lane, d0, d1);
                if (lane == 0) {
                    xb[n] = fmaxf(d0 + bfu[n], 0.f);
                    xb[n + 1] = fmaxf(d1 + bfu[n + 1], 0.f);
                }
            }
            __syncwarp();
            for (int n = 0; n < FOURE; n += 2) {
                float d0, d1;
                wdot2(xb, Wg1 + (size_t)n * HID, Wg1 + (size_t)(n + 1) * HID, HID, lane, d0, d1);
                if (lane == 0) { xa[n] = tanhf(d0); xa[n + 1] = tanhf(d1); }
            }
            __syncwarp();
            for (int n = 0; n < NEXP; n += 2) {
                float d0, d1;
                wdot2(xa, Wg2 + (size_t)n * FOURE, Wg2 + (size_t)(n + 1) * FOURE, FOURE, lane, d0, d1);
                if (lane == 0) { xb[n] = d0; xb[n + 1] = d1; }
            }
            __syncwarp();
            top2_write(xb[lane], xb[lane + 32], lane, b, out, out_size, false);
        }
    }
}

// ---------------- launch -----------------------------------------------------
extern "C" void kernel_launch(void* const* d_in, const int* in_sizes, int n_in,
                              void* d_out, int out_size)
{
    const float* mm    = (const float*)d_in[0];
    const float* qf    = (const float*)d_in[1];
    const float* W_qe1 = (const float*)d_in[2];
    const float* b_qe1 = (const float*)d_in[3];
    const float* W_qe2 = (const float*)d_in[4];
    const float* b_qe2 = (const float*)d_in[5];
    const float* W_fus = (const float*)d_in[6];
    const float* b_fus = (const float*)d_in[7];
    const float* W_g1  = (const float*)d_in[8];
    const float* W_g2  = (const float*)d_in[9];
    float* out = (float*)d_out;

    bf16 *qfh, *qfl, *mmh, *mml, *x1h, *x1l, *x2h, *x2l, *x3h, *x3l, *x4h, *x4l;
    bf16 *w1h, *w1l, *w2h, *w2l, *wfh, *wfl, *g1h, *g1l, *g2h, *g2l;
    float* pl;
    cudaGetSymbolAddress((void**)&qfh, g_qfh); cudaGetSymbolAddress((void**)&qfl, g_qfl);
    cudaGetSymbolAddress((void**)&mmh, g_mmh); cudaGetSymbolAddress((void**)&mml, g_mml);
    cudaGetSymbolAddress((void**)&x1h, g_x1h); cudaGetSymbolAddress((void**)&x1l, g_x1l);
    cudaGetSymbolAddress((void**)&x2h, g_x2h); cudaGetSymbolAddress((void**)&x2l, g_x2l);
    cudaGetSymbolAddress((void**)&x3h, g_x3h); cudaGetSymbolAddress((void**)&x3l, g_x3l);
    cudaGetSymbolAddress((void**)&x4h, g_x4h); cudaGetSymbolAddress((void**)&x4l, g_x4l);
    cudaGetSymbolAddress((void**)&w1h, g_w1h); cudaGetSymbolAddress((void**)&w1l, g_w1l);
    cudaGetSymbolAddress((void**)&w2h, g_w2h); cudaGetSymbolAddress((void**)&w2l, g_w2l);
    cudaGetSymbolAddress((void**)&wfh, g_wfh); cudaGetSymbolAddress((void**)&wfl, g_wfl);
    cudaGetSymbolAddress((void**)&g1h, g_g1h); cudaGetSymbolAddress((void**)&g1l, g_g1l);
    cudaGetSymbolAddress((void**)&g2h, g_g2h); cudaGetSymbolAddress((void**)&g2l, g_g2l);
    cudaGetSymbolAddress((void**)&pl, g_l);

    zero_cnt<<<1, 1>>>();

    const int NA = BTOK * DIN;
    split2<<<(NA + 255) / 256, 256>>>(qf, qfh, qfl, NA);
    split2<<<(NA + 255) / 256, 256>>>(mm, mmh, mml, NA);
    split2<<<(HID * DIN + 255) / 256, 256>>>(W_qe1, w1h, w1l, HID * DIN);
    split2<<<(HID * HID + 255) / 256, 256>>>(W_qe2, w2h, w2l, HID * HID);
    split2<<<(HID * 2 * HID + 255) / 256, 256>>>(W_fus, wfh, wfl, HID * 2 * HID);
    split2<<<(FOURE * HID + 255) / 256, 256>>>(W_g1, g1h, g1l, FOURE * HID);
    split2<<<(NEXP * FOURE + 255) / 256, 256>>>(W_g2, g2h, g2l, NEXP * FOURE);

    const dim3 blk(256);
    LArgs a;
    // L1: x1 = relu(qf @ W1^T + b1)
    a = LArgs{qfh, qfl, nullptr, nullptr, w1h, w1l, b_qe1,
              x1h, x1l, nullptr, DIN, DIN, HID, 1, 0};
    mma_layer<<<dim3(HID / 64, BTOK / 128), blk>>>(a);
    // L2: x2 = x1 @ W2^T + b2
    a = LArgs{x1h, x1l, nullptr, nullptr, w2h, w2l, b_qe2,
              x2h, x2l, nullptr, HID, HID, HID, 0, 0};
    mma_layer<<<dim3(HID / 64, BTOK / 128), blk>>>(a);
    // L3: x3 = relu([mm | x2] @ Wf^T + bf)
    a = LArgs{mmh, mml, x2h, x2l, wfh, wfl, b_fus,
              x3h, x3l, nullptr, HID, 2 * HID, HID, 1, 0};
    mma_layer<<<dim3(HID / 64, BTOK / 128), blk>>>(a);
    // L4: x4 = tanh(x3 @ Wg1^T)
    a = LArgs{x3h, x3l, nullptr, nullptr, g1h, g1l, nullptr,
              x4h, x4l, nullptr, HID, HID, FOURE, 2, 0};
    mma_layer<<<dim3(FOURE / 64, BTOK / 128), blk>>>(a);
    // L5: logits = x4 @ Wg2^T  (fp32 out)
    a = LArgs{x4h, x4l, nullptr, nullptr, g2h, g2l, nullptr,
              nullptr, nullptr, pl, FOURE, FOURE, NEXP, 0, 1};
    mma_layer<<<dim3(NEXP / 64, BTOK / 128), blk>>>(a);

    epilogue_kernel<<<BTOK / 8, 256>>>(out, out_size);
    exact_fix<<<256, 256>>>(mm, qf, W_qe1, b_qe1, W_qe2, b_qe2,
                            W_fus, b_fus, W_g1, W_g2, out, out_size);
}

// round 16
// speedup vs baseline: 1.8952x; 1.1426x over previous
#include <cuda_runtime.h>
#include <cuda_bf16.h>
#include <cstdint>

#define BTOK  65536
#define HID   512
#define DIN   512
#define NEXP  64
#define FOURE 256
#define TAU   2e-5f

typedef __nv_bfloat16 bf16;
typedef unsigned int u32;

// ---------------- scratch (static __device__, no allocation) ----------------
__device__ __align__(16) bf16 g_qfh[(size_t)BTOK * DIN];
__device__ __align__(16) bf16 g_qfl[(size_t)BTOK * DIN];
__device__ __align__(16) bf16 g_mmh[(size_t)BTOK * HID];
__device__ __align__(16) bf16 g_mml[(size_t)BTOK * HID];
__device__ __align__(16) bf16 g_x1h[(size_t)BTOK * HID];
__device__ __align__(16) bf16 g_x1l[(size_t)BTOK * HID];
__device__ __align__(16) bf16 g_x2h[(size_t)BTOK * HID];
__device__ __align__(16) bf16 g_x2l[(size_t)BTOK * HID];
__device__ __align__(16) bf16 g_x3h[(size_t)BTOK * HID];
__device__ __align__(16) bf16 g_x3l[(size_t)BTOK * HID];
__device__ __align__(16) bf16 g_x4h[(size_t)BTOK * FOURE];
__device__ __align__(16) bf16 g_x4l[(size_t)BTOK * FOURE];
__device__ __align__(16) bf16 g_w1h[(size_t)HID * DIN];
__device__ __align__(16) bf16 g_w1l[(size_t)HID * DIN];
__device__ __align__(16) bf16 g_w2h[(size_t)HID * HID];
__device__ __align__(16) bf16 g_w2l[(size_t)HID * HID];
__device__ __align__(16) bf16 g_wfh[(size_t)HID * 2 * HID];
__device__ __align__(16) bf16 g_wfl[(size_t)HID * 2 * HID];
__device__ __align__(16) bf16 g_g1h[(size_t)FOURE * HID];
__device__ __align__(16) bf16 g_g1l[(size_t)FOURE * HID];
__device__ __align__(16) bf16 g_g2h[(size_t)NEXP * FOURE];
__device__ __align__(16) bf16 g_g2l[(size_t)NEXP * FOURE];
__device__ float g_l[(size_t)BTOK * NEXP];
__device__ int   g_list[BTOK];
__device__ int   g_count;

// ---------------- helpers ----------------------------------------------------
__device__ __forceinline__ u32 smem_u32(const void* p) {
    u32 a;
    asm("{ .reg .u64 t; cvta.to.shared.u64 t, %1; cvt.u32.u64 %0, t; }" : "=r"(a) : "l"(p));
    return a;
}
// swizzled byte offset inside a [rows][32 bf16] tile (row stride 64B).
__device__ __forceinline__ int swoff(int r, int c8) {
    return r * 64 + ((((c8 >> 3) ^ ((r >> 1) & 3)) & 3) << 4);
}
__device__ __forceinline__ void ldsm4(u32* r, u32 a) {
    asm volatile("ldmatrix.sync.aligned.m8n8.x4.shared.b16 {%0,%1,%2,%3}, [%4];"
                 : "=r"(r[0]), "=r"(r[1]), "=r"(r[2]), "=r"(r[3]) : "r"(a));
}
__device__ __forceinline__ void hmma(float* d, const u32* a, u32 b0, u32 b1) {
    asm volatile(
        "mma.sync.aligned.m16n8k16.row.col.f32.bf16.bf16.f32 "
        "{%0,%1,%2,%3}, {%4,%5,%6,%7}, {%8,%9}, {%0,%1,%2,%3};"
        : "+f"(d[0]), "+f"(d[1]), "+f"(d[2]), "+f"(d[3])
        : "r"(a[0]), "r"(a[1]), "r"(a[2]), "r"(a[3]), "r"(b0), "r"(b1));
}

// ---------------- split fp32 -> hi/lo bf16 -----------------------------------
__global__ void split2(const float* __restrict__ x, bf16* __restrict__ h,
                       bf16* __restrict__ l, int n)
{
    int i = blockIdx.x * blockDim.x + threadIdx.x;
    if (i >= n) return;
    float v = x[i];
    bf16 a = __float2bfloat16(v);
    h[i] = a;
    l[i] = __float2bfloat16(v - __bfloat162float(a));
}

__global__ void zero_cnt() { g_count = 0; }

// ---------------- HMMA bf16x2-split layer (double-buffered) ------------------
// CTA 128x64 (8 warps, warp tile 32x32), K tiles of 32, 3 products per k16.
// Double buffer: LDG t+1 into regs before computing t; ONE sync per tile.
struct LArgs {
    const bf16 *a0h, *a0l, *a1h, *a1l;
    const bf16 *bh, *bl;
    const float* bias;
    bf16 *oh, *ol;
    float* of;
    int K0, K, N, act, outf;
};

#define LDG_T(kt)                                                             \
    {                                                                         \
        const bool s0 = (kt) < ar.K0;                                         \
        const int stride = s0 ? ar.K0 : (ar.K - ar.K0);                       \
        const int goff = s0 ? (kt) : ((kt) - ar.K0);                          \
        const bf16* ah = s0 ? ar.a0h : ar.a1h;                                \
        const bf16* al = s0 ? ar.a0l : ar.a1l;                                \
        _Pragma("unroll")                                                     \
        for (int c = 0; c < 2; c++) {                                         \
            int fidx = c * 256 + tid, r = fidx >> 2, c8 = (fidx & 3) * 8;     \
            const size_t go = (size_t)(m0 + r) * stride + goff + c8;          \
            rAh[c] = *(const uint4*)(ah + go);                                \
            rAl[c] = *(const uint4*)(al + go);                                \
        }                                                                     \
        {                                                                     \
            int r = tid >> 2, c8 = (tid & 3) * 8;                             \
            const size_t go = (size_t)(n0 + r) * ar.K + (kt) + c8;            \
            rBh = *(const uint4*)(ar.bh + go);                                \
            rBl = *(const uint4*)(ar.bl + go);                                \
        }                                                                     \
    }

#define STS_T(buf)                                                            \
    {                                                                         \
        _Pragma("unroll")                                                     \
        for (int c = 0; c < 2; c++) {                                         \
            int fidx = c * 256 + tid, r = fidx >> 2, c8 = (fidx & 3) * 8;     \
            *(uint4*)((char*)As[buf][0] + swoff(r, c8)) = rAh[c];             \
            *(uint4*)((char*)As[buf][1] + swoff(r, c8)) = rAl[c];             \
        }                                                                     \
        {                                                                     \
            int r = tid >> 2, c8 = (tid & 3) * 8;                             \
            *(uint4*)((char*)Bs[buf][0] + swoff(r, c8)) = rBh;                \
            *(uint4*)((char*)Bs[buf][1] + swoff(r, c8)) = rBl;                \
        }                                                                     \
    }

__global__ void __launch_bounds__(256, 2) mma_layer(LArgs ar)
{
    __shared__ __align__(16) bf16 As[2][2][128 * 32];
    __shared__ __align__(16) bf16 Bs[2][2][64 * 32];
    const int tid = threadIdx.x, wid = tid >> 5, lane = tid & 31;
    const int m0 = blockIdx.y * 128, n0 = blockIdx.x * 64;
    const int mbase = (wid & 3) * 32, nbase = (wid >> 2) * 32;

    float acc[2][4][4];
#pragma unroll
    for (int i = 0; i < 2; i++)
#pragma unroll
        for (int j = 0; j < 4; j++)
#pragma unroll
            for (int c = 0; c < 4; c++) acc[i][j][c] = 0.f;

    uint4 rAh[2], rAl[2], rBh, rBl;

    LDG_T(0);
    STS_T(0);
    __syncthreads();

    int p = 0;
    for (int kt = 0; kt < ar.K; kt += 32) {
        const bool nxt = (kt + 32) < ar.K;
        if (nxt) LDG_T(kt + 32);

        const u32 asb0 = smem_u32(As[p][0]), asb1 = smem_u32(As[p][1]);
        const u32 bsb0 = smem_u32(Bs[p][0]), bsb1 = smem_u32(Bs[p][1]);
#pragma unroll
        for (int kh = 0; kh < 32; kh += 16) {
            u32 a[2][2][4], b[2][2][4];
            {
                const int rr = (lane & 7) + ((lane >> 3) & 1) * 8;
                const int c8 = kh + (lane >> 4) * 8;
#pragma unroll
                for (int i = 0; i < 2; i++) {
                    const int off = swoff(mbase + i * 16 + rr, c8);
                    ldsm4(a[0][i], asb0 + off);
                    ldsm4(a[1][i], asb1 + off);
                }
            }
            {
                const int mi = lane >> 3;
#pragma unroll
                for (int pb = 0; pb < 2; pb++) {
                    const int row = nbase + (pb * 2 + (mi >> 1)) * 8 + (lane & 7);
                    const int c8 = kh + (mi & 1) * 8;
                    const int off = swoff(row, c8);
                    ldsm4(b[0][pb], bsb0 + off);
                    ldsm4(b[1][pb], bsb1 + off);
                }
            }
#pragma unroll
            for (int pr = 0; pr < 3; pr++) {
                const int sa = (pr == 2) ? 1 : 0;
                const int sb = (pr == 1) ? 1 : 0;
#pragma unroll
                for (int i = 0; i < 2; i++)
#pragma unroll
                    for (int j = 0; j < 4; j++) {
                        const int pb = j >> 1, ix = (j & 1) * 2;
                        hmma(acc[i][j], a[sa][i], b[sb][pb][ix], b[sb][pb][ix + 1]);
                    }
            }
        }

        if (nxt) {
            STS_T(p ^ 1);
            __syncthreads();
        }
        p ^= 1;
    }

    // epilogue: bias + act, write hi/lo splits (or f32 for logits)
    const int g = lane >> 2, t = lane & 3;
#pragma unroll
    for (int i = 0; i < 2; i++)
#pragma unroll
        for (int j = 0; j < 4; j++) {
            const int col = n0 + nbase + j * 8 + 2 * t;
            const float bb0 = ar.bias ? ar.bias[col] : 0.f;
            const float bb1 = ar.bias ? ar.bias[col + 1] : 0.f;
#pragma unroll
            for (int h = 0; h < 2; h++) {
                const int R = m0 + mbase + i * 16 + g + h * 8;
                float v0 = acc[i][j][h * 2 + 0] + bb0;
                float v1 = acc[i][j][h * 2 + 1] + bb1;
                if (ar.act == 1)      { v0 = fmaxf(v0, 0.f); v1 = fmaxf(v1, 0.f); }
                else if (ar.act == 2) { v0 = tanhf(v0);      v1 = tanhf(v1); }
                const size_t o = (size_t)R * ar.N + col;
                if (ar.outf) {
                    *(float2*)(ar.of + o) = make_float2(v0, v1);
                } else {
                    bf16 h0 = __float2bfloat16(v0), h1 = __float2bfloat16(v1);
                    __nv_bfloat162 hv; hv.x = h0; hv.y = h1;
                    *(__nv_bfloat162*)(ar.oh + o) = hv;
                    __nv_bfloat162 lv;
                    lv.x = __float2bfloat16(v0 - __bfloat162float(h0));
                    lv.y = __float2bfloat16(v1 - __bfloat162float(h1));
                    *(__nv_bfloat162*)(ar.ol + o) = lv;
                }
            }
        }
}

// ---------------- warp softmax/top2 ------------------------------------------
__device__ __forceinline__ void top2_write(float l0, float l1, int lane, int b,
                                           float* out, int out_size, bool flag_mode)
{
    const int OFF_L = BTOK * NEXP, OFF_W = 2 * BTOK * NEXP, OFF_I = 3 * BTOK * NEXP;
    const bool wl = out_size >= OFF_W, ww = out_size >= OFF_I;
    const bool wi = out_size >= OFF_I + 2 * BTOK;

    float m = fmaxf(l0, l1);
#pragma unroll
    for (int o = 16; o; o >>= 1) m = fmaxf(m, __shfl_xor_sync(0xffffffffu, m, o));
    float e0 = expf(l0 - m), e1 = expf(l1 - m);
    float sd = e0 + e1;
#pragma unroll
    for (int o = 16; o; o >>= 1) sd += __shfl_xor_sync(0xffffffffu, sd, o);
    float w0 = e0 / sd, w1 = e1 / sd;

    float bv; int bi;
    if (w0 >= w1) { bv = w0; bi = lane; } else { bv = w1; bi = lane + 32; }
#pragma unroll
    for (int o = 16; o; o >>= 1) {
        float ov = __shfl_xor_sync(0xffffffffu, bv, o);
        int oi = __shfl_xor_sync(0xffffffffu, bi, o);
        if (ov > bv || (ov == bv && oi < bi)) { bv = ov; bi = oi; }
    }
    float d0 = (lane == bi) ? -1.f : w0;
    float d1 = (lane + 32 == bi) ? -1.f : w1;
    float bv2; int bi2;
    if (d0 >= d1) { bv2 = d0; bi2 = lane; } else { bv2 = d1; bi2 = lane + 32; }
#pragma unroll
    for (int o = 16; o; o >>= 1) {
        float ov = __shfl_xor_sync(0xffffffffu, bv2, o);
        int oi = __shfl_xor_sync(0xffffffffu, bi2, o);
        if (ov > bv2 || (ov == bv2 && oi < bi2)) { bv2 = ov; bi2 = oi; }
    }
    if (flag_mode) {
        float f0 = (lane == bi || lane == bi2) ? -1.f : w0;
        float f1 = (lane + 32 == bi || lane + 32 == bi2) ? -1.f : w1;
        float bv3 = fmaxf(f0, f1);
#pragma unroll
        for (int o = 16; o; o >>= 1) bv3 = fmaxf(bv3, __shfl_xor_sync(0xffffffffu, bv3, o));
        if (lane == 0 && (bv - bv2 < TAU || bv2 - bv3 < TAU)) {
            int p = atomicAdd(&g_count, 1);
            if (p < BTOK) g_list[p] = b;
        }
    }
    const float den = bv + bv2 + 1e-6f;
    const float r1 = bv / den, r2 = bv2 / den;
    const size_t base = (size_t)b * NEXP;
    out[base + lane]      = (lane == bi) ? r1 : (lane == bi2) ? r2 : 0.f;
    out[base + lane + 32] = (lane + 32 == bi) ? r1 : (lane + 32 == bi2) ? r2 : 0.f;
    if (wl) { out[OFF_L + base + lane] = l0; out[OFF_L + base + lane + 32] = l1; }
    if (ww) { out[OFF_W + base + lane] = w0; out[OFF_W + base + lane + 32] = w1; }
    if (wi && lane == 0) {
        out[OFF_I + (size_t)b * 2]     = (float)bi;
        out[OFF_I + (size_t)b * 2 + 1] = (float)bi2;
    }
}

__global__ __launch_bounds__(256) void epilogue_kernel(float* __restrict__ out, int out_size)
{
    const int lane = threadIdx.x & 31;
    const int b = blockIdx.x * 8 + (threadIdx.x >> 5);
    const size_t base = (size_t)b * NEXP;
    top2_write(g_l[base + lane], g_l[base + lane + 32], lane, b, out, out_size, true);
}

// ---------------- exact path: warp-cooperative Kahan recompute ---------------
__device__ __forceinline__ void wdot2(const float* __restrict__ x,
                                      const float* __restrict__ w0,
                                      const float* __restrict__ w1,
                                      int K, int lane, float& r0, float& r1)
{
    float s0 = 0.f, c0 = 0.f, s1 = 0.f, c1 = 0.f;
    for (int k = lane; k < K; k += 32) {
        const float xv = x[k];
        { float y = fmaf(xv, w0[k], -c0); float t = s0 + y; c0 = (t - s0) - y; s0 = t; }
        { float y = fmaf(xv, w1[k], -c1); float t = s1 + y; c1 = (t - s1) - y; s1 = t; }
    }
    s0 -= c0; s1 -= c1;
#pragma unroll
    for (int o = 16; o; o >>= 1) {
        s0 += __shfl_xor_sync(0xffffffffu, s0, o);
        s1 += __shfl_xor_sync(0xffffffffu, s1, o);
    }
    r0 = s0; r1 = s1;
}

__global__ __launch_bounds__(256) void exact_fix(
    const float* mm, const float* qf,
    const float* W1, const float* b1, const float* W2, const float* b2,
    const float* Wf, const float* bfu, const float* Wg1, const float* Wg2,
    float* out, int out_size)
{
    __shared__ float sA[8][1024];
    __shared__ float sB[8][512];
    const int wid = threadIdx.x >> 5, lane = threadIdx.x & 31;
    const int cnt = g_count;
    for (int base = blockIdx.x * 8; base < cnt; base += gridDim.x * 8) {
        const int idx = base + wid;
        if (idx < cnt) {
            const int b = g_list[idx];
            float* xa = sA[wid];
            float* xb = sB[wid];
            for (int k = lane; k < DIN; k += 32) xa[k] = qf[(size_t)b * DIN + k];
            __syncwarp();
            for (int n = 0; n < HID; n += 2) {
                float d0, d1;
                wdot2(xa, W1 + (size_t)n * DIN, W1 + (size_t)(n + 1) * DIN, DIN, lane, d0, d1);
                if (lane == 0) {
                    xb[n] = fmaxf(d0 + b1[n], 0.f);
                    xb[n + 1] = fmaxf(d1 + b1[n + 1], 0.f);
                }
            }
            __syncwarp();
            for (int n = 0; n < HID; n += 2) {
                float d0, d1;
                wdot2(xb, W2 + (size_t)n * HID, W2 + (size_t)(n + 1) * HID, HID, lane, d0, d1);
                if (lane == 0) { xa[HID + n] = d0 + b2[n]; xa[HID + n + 1] = d1 + b2[n + 1]; }
            }
            __syncwarp();
            for (int k = lane; k < HID; k += 32) xa[k] = mm[(size_t)b * HID + k];
            __syncwarp();
            for (int n = 0; n < HID; n += 2) {
                float d0, d1;
                wdot2(xa, Wf + (size_t)n * 2 * HID, Wf + (size_t)(n + 1) * 2 * HID, 2 * HID, lane, d0, d1);
                if (lane == 0) {
                    xb[n] = fmaxf(d0 + bfu[n], 0.f);
                    xb[n + 1] = fmaxf(d1 + bfu[n + 1], 0.f);
                }
            }
            __syncwarp();
            for (int n = 0; n < FOURE; n += 2) {
                float d0, d1;
                wdot2(xb, Wg1 + (size_t)n * HID, Wg1 + (size_t)(n + 1) * HID, HID, lane, d0, d1);
                if (lane == 0) { xa[n] = tanhf(d0); xa[n + 1] = tanhf(d1); }
            }
            __syncwarp();
            for (int n = 0; n < NEXP; n += 2) {
                float d0, d1;
                wdot2(xa, Wg2 + (size_t)n * FOURE, Wg2 + (size_t)(n + 1) * FOURE, FOURE, lane, d0, d1);
                if (lane == 0) { xb[n] = d0; xb[n + 1] = d1; }
            }
            __syncwarp();
            top2_write(xb[lane], xb[lane + 32], lane, b, out, out_size, false);
        }
    }
}

// ---------------- launch -----------------------------------------------------
extern "C" void kernel_launch(void* const* d_in, const int* in_sizes, int n_in,
                              void* d_out, int out_size)
{
    const float* mm    = (const float*)d_in[0];
    const float* qf    = (const float*)d_in[1];
    const float* W_qe1 = (const float*)d_in[2];
    const float* b_qe1 = (const float*)d_in[3];
    const float* W_qe2 = (const float*)d_in[4];
    const float* b_qe2 = (const float*)d_in[5];
    const float* W_fus = (const float*)d_in[6];
    const float* b_fus = (const float*)d_in[7];
    const float* W_g1  = (const float*)d_in[8];
    const float* W_g2  = (const float*)d_in[9];
    float* out = (float*)d_out;

    bf16 *qfh, *qfl, *mmh, *mml, *x1h, *x1l, *x2h, *x2l, *x3h, *x3l, *x4h, *x4l;
    bf16 *w1h, *w1l, *w2h, *w2l, *wfh, *wfl, *g1h, *g1l, *g2h, *g2l;
    float* pl;
    cudaGetSymbolAddress((void**)&qfh, g_qfh); cudaGetSymbolAddress((void**)&qfl, g_qfl);
    cudaGetSymbolAddress((void**)&mmh, g_mmh); cudaGetSymbolAddress((void**)&mml, g_mml);
    cudaGetSymbolAddress((void**)&x1h, g_x1h); cudaGetSymbolAddress((void**)&x1l, g_x1l);
    cudaGetSymbolAddress((void**)&x2h, g_x2h); cudaGetSymbolAddress((void**)&x2l, g_x2l);
    cudaGetSymbolAddress((void**)&x3h, g_x3h); cudaGetSymbolAddress((void**)&x3l, g_x3l);
    cudaGetSymbolAddress((void**)&x4h, g_x4h); cudaGetSymbolAddress((void**)&x4l, g_x4l);
    cudaGetSymbolAddress((void**)&w1h, g_w1h); cudaGetSymbolAddress((void**)&w1l, g_w1l);
    cudaGetSymbolAddress((void**)&w2h, g_w2h); cudaGetSymbolAddress((void**)&w2l, g_w2l);
    cudaGetSymbolAddress((void**)&wfh, g_wfh); cudaGetSymbolAddress((void**)&wfl, g_wfl);
    cudaGetSymbolAddress((void**)&g1h, g_g1h); cudaGetSymbolAddress((void**)&g1l, g_g1l);
    cudaGetSymbolAddress((void**)&g2h, g_g2h); cudaGetSymbolAddress((void**)&g2l, g_g2l);
    cudaGetSymbolAddress((void**)&pl, g_l);

    zero_cnt<<<1, 1>>>();

    const int NA = BTOK * DIN;
    split2<<<(NA + 255) / 256, 256>>>(qf, qfh, qfl, NA);
    split2<<<(NA + 255) / 256, 256>>>(mm, mmh, mml, NA);
    split2<<<(HID * DIN + 255) / 256, 256>>>(W_qe1, w1h, w1l, HID * DIN);
    split2<<<(HID * HID + 255) / 256, 256>>>(W_qe2, w2h, w2l, HID * HID);
    split2<<<(HID * 2 * HID + 255) / 256, 256>>>(W_fus, wfh, wfl, HID * 2 * HID);
    split2<<<(FOURE * HID + 255) / 256, 256>>>(W_g1, g1h, g1l, FOURE * HID);
    split2<<<(NEXP * FOURE + 255) / 256, 256>>>(W_g2, g2h, g2l, NEXP * FOURE);

    const dim3 blk(256);
    LArgs a;
    // L1: x1 = relu(qf @ W1^T + b1)
    a = LArgs{qfh, qfl, nullptr, nullptr, w1h, w1l, b_qe1,
              x1h, x1l, nullptr, DIN, DIN, HID, 1, 0};
    mma_layer<<<dim3(HID / 64, BTOK / 128), blk>>>(a);
    // L2: x2 = x1 @ W2^T + b2
    a = LArgs{x1h, x1l, nullptr, nullptr, w2h, w2l, b_qe2,
              x2h, x2l, nullptr, HID, HID, HID, 0, 0};
    mma_layer<<<dim3(HID / 64, BTOK / 128), blk>>>(a);
    // L3: x3 = relu([mm | x2] @ Wf^T + bf)
    a = LArgs{mmh, mml, x2h, x2l, wfh, wfl, b_fus,
              x3h, x3l, nullptr, HID, 2 * HID, HID, 1, 0};
    mma_layer<<<dim3(HID / 64, BTOK / 128), blk>>>(a);
    // L4: x4 = tanh(x3 @ Wg1^T)
    a = LArgs{x3h, x3l, nullptr, nullptr, g1h, g1l, nullptr,
              x4h, x4l, nullptr, HID, HID, FOURE, 2, 0};
    mma_layer<<<dim3(FOURE / 64, BTOK / 128), blk>>>(a);
    // L5: logits = x4 @ Wg2^T  (fp32 out)
    a = LArgs{x4h, x4l, nullptr, nullptr, g2h, g2l, nullptr,
              nullptr, nullptr, pl, FOURE, FOURE, NEXP, 0, 1};
    mma_layer<<<dim3(NEXP / 64, BTOK / 128), blk>>>(a);

    epilogue_kernel<<<BTOK / 8, 256>>>(out, out_size);
    exact_fix<<<256, 256>>>(mm, qf, W_qe1, b_qe1, W_qe2, b_qe2,
                            W_fus, b_fus, W_g1, W_g2, out, out_size);
}